// round 7
// baseline (speedup 1.0000x reference)
#include <cuda_runtime.h>
#include <cstdint>

#define VOCAB   32000
#define VWORDS  8000          // VOCAB / 4 (float4 words), < 2^13
#define TPB     512
#define SWORDS  512           // float4 words per stage (8 KB)
#define NSTAGES 16
#define DEPTH   4
#define NBINS   2048
#define QCAP    128           // max gathered quads (-> 512 candidates)

typedef unsigned long long u64;
typedef unsigned int       u32;

__device__ int g_done_ctr = 0;

__device__ __forceinline__ u32 f2s(float f) {
    u32 b = __float_as_uint(f);
    return (b & 0x80000000u) ? ~b : (b | 0x80000000u);
}
__device__ __forceinline__ float s2f(u32 u) {
    u32 b = (u & 0x80000000u) ? (u & 0x7fffffffu) : ~u;
    return __uint_as_float(b);
}

__device__ __forceinline__ u32 block_scan_u32(u32 v, u32* smem16, int tid) {
    int lane = tid & 31, wid = tid >> 5;
    u32 x = v;
#pragma unroll
    for (int o = 1; o < 32; o <<= 1) {
        u32 t = __shfl_up_sync(0xffffffffu, x, o);
        if (lane >= o) x += t;
    }
    if (lane == 31) smem16[wid] = x;
    __syncthreads();
    if (wid == 0) {
        u32 w = (lane < 16) ? smem16[lane] : 0u;
#pragma unroll
        for (int o = 1; o < 16; o <<= 1) {
            u32 t = __shfl_up_sync(0xffffffffu, w, o);
            if (lane >= o) w += t;
        }
        if (lane < 16) smem16[lane] = w;
    }
    __syncthreads();
    return x + (wid ? smem16[wid - 1] : 0u);
}

__device__ __forceinline__ float block_scan_f32(float v, float* smem16, int tid) {
    int lane = tid & 31, wid = tid >> 5;
    float x = v;
#pragma unroll
    for (int o = 1; o < 32; o <<= 1) {
        float t = __shfl_up_sync(0xffffffffu, x, o);
        if (lane >= o) x += t;
    }
    if (lane == 31) smem16[wid] = x;
    __syncthreads();
    if (wid == 0) {
        float w = (lane < 16) ? smem16[lane] : 0.0f;
#pragma unroll
        for (int o = 1; o < 16; o <<= 1) {
            float t = __shfl_up_sync(0xffffffffu, w, o);
            if (lane >= o) w += t;
        }
        if (lane < 16) smem16[lane] = w;
    }
    __syncthreads();
    return x + (wid ? smem16[wid - 1] : 0.0f);
}

// branchless descending top-6 insert; alternate int/float minmax pipes.
// keys are positive finite floats bit-packed with quad idx -> int order == float order.
__device__ __forceinline__ void ins6(u32 k, u32 (&tv)[6]) {
#pragma unroll
    for (int q = 0; q < 6; q++) {
        if (q & 1) {
            float a = __uint_as_float(tv[q]), b = __uint_as_float(k);
            float hi = fmaxf(a, b), lo = fminf(a, b);
            tv[q] = __float_as_uint(hi); k = __float_as_uint(lo);
        } else {
            u32 hi = max(tv[q], k), lo = min(tv[q], k);
            tv[q] = hi; k = lo;
        }
    }
}

__device__ __forceinline__ float ex2f(float y) {
    float r;
    asm("ex2.approx.f32 %0, %1;" : "=f"(r) : "f"(y));
    return r;
}

// 4 elements: Z accumulate + single quad-max key insert
__device__ __forceinline__ void proc4(float4 v, int j, float c1,
                                      float& z0, float& z1, float& z2, float& z3,
                                      u32 (&tv)[6]) {
    float e0 = ex2f(v.x * c1), e1 = ex2f(v.y * c1);
    float e2 = ex2f(v.z * c1), e3 = ex2f(v.w * c1);
    z0 += e0; z1 += e1; z2 += e2; z3 += e3;
    float m = fmaxf(fmaxf(e0, e1), fmaxf(e2, e3));
    u32 k = (__float_as_uint(m) & 0xFFFFE000u) | (u32)j;
    ins6(k, tv);
}

__global__ __launch_bounds__(TPB, 2)
void sampler_row_kernel(const float* __restrict__ logits,
                        const float* __restrict__ gumbel,
                        const float* __restrict__ temp_p,
                        const float* __restrict__ topp_p,
                        const int*   __restrict__ topk_p,
                        const float* __restrict__ thr_p,
                        float* __restrict__ out, int N)
{
    __shared__ float4 s_stage[DEPTH][SWORDS];   // 32 KB; reused as sort buffer
    __shared__ u32    s_hist[NBINS];            // 8 KB
    __shared__ u32    s_g32[QCAP];              // 512 B (gathered quad keys)
    __shared__ float  s_pref[512];              // 2 KB
    __shared__ u32    s_t16[16];
    __shared__ float  s_f16[16];
    __shared__ u64    s_red64[16];
    __shared__ float  s_redf[16];
    __shared__ float  s_Z;
    __shared__ int    s_bin, s_gcnt, s_vmin, s_snum, s_last;

    const int tid  = threadIdx.x;
    const int row  = blockIdx.x;
    const int wid  = tid >> 5;
    const int lane = tid & 31;

    const float invT = 1.0f / (*temp_p);
    const float c1   = 1.44269504088896341f * invT;   // log2(e)/T
    const float topP = *topp_p;
    int Kw = *topk_p;
    Kw = max(1, min(Kw, 512));
    const int KQ = min(Kw, QCAP);    // quad-rank target (covers top-KQ elements)

    const float* rowp = logits + (size_t)row * VOCAB;
    const float4* rp  = (const float4*)rowp;

    if (tid == 0) { s_gcnt = 0; s_vmin = 1 << 30; }
#pragma unroll
    for (int q = 0; q < NBINS / TPB; q++) s_hist[tid + q * TPB] = 0u;

    u32 tv[6];
#pragma unroll
    for (int q = 0; q < 6; q++) tv[q] = 0u;
    float z0 = 0.f, z1 = 0.f, z2 = 0.f, z3 = 0.f;

#define ISSUE(s)                                                              \
    do {                                                                      \
        int _j = (s) * SWORDS + tid;                                          \
        if ((s) < NSTAGES && _j < VWORDS) {                                   \
            u32 _dst = (u32)__cvta_generic_to_shared(                         \
                &s_stage[(s) & (DEPTH - 1)][tid]);                            \
            asm volatile("cp.async.cg.shared.global [%0], [%1], 16;"          \
                         :: "r"(_dst), "l"(rp + _j));                         \
        }                                                                     \
        asm volatile("cp.async.commit_group;");                               \
    } while (0)

    ISSUE(0); ISSUE(1); ISSUE(2); ISSUE(3);

#pragma unroll 1
    for (int s = 0; s < NSTAGES; s++) {
        asm volatile("cp.async.wait_group %0;" :: "n"(DEPTH - 1));
        int j = s * SWORDS + tid;
        if (j < VWORDS) {
            float4 v = s_stage[s & (DEPTH - 1)][tid];
            proc4(v, j, c1, z0, z1, z2, z3, tv);
        }
        ISSUE(s + DEPTH);
    }
    asm volatile("cp.async.wait_group 0;");

    float zsum = (z0 + z1) + (z2 + z3);

    // ---- block-reduce Z ----
#pragma unroll
    for (int off = 16; off; off >>= 1)
        zsum += __shfl_down_sync(0xffffffffu, zsum, off);
    if (lane == 0) s_redf[wid] = zsum;
    __syncthreads();
    if (tid == 0) {
        float z = 0.0f;
        for (int w = 0; w < 16; w++) z += s_redf[w];
        s_Z = z;
    }

    // ---- histogram of quad keys (top 11 bits) ----
#pragma unroll
    for (int q = 0; q < 6; q++)
        atomicAdd(&s_hist[tv[q] >> 21], 1u);
    __syncthreads();

    // ---- suffix scan from highest bin; locate rank-KQ bin ----
    u32 c4[4]; u32 tsum = 0;
#pragma unroll
    for (int q = 0; q < 4; q++) {
        int bin = (NBINS - 1) - (tid * 4 + q);
        c4[q] = s_hist[bin];
        tsum += c4[q];
    }
    u32 incl = block_scan_u32(tsum, s_t16, tid);
    {
        u32 cum = incl - tsum;
#pragma unroll
        for (int q = 0; q < 4; q++) {
            if (cum < (u32)KQ && cum + c4[q] >= (u32)KQ)
                s_bin = (NBINS - 1) - (tid * 4 + q);
            cum += c4[q];
        }
    }
    __syncthreads();
    const int binSel = s_bin;

    // ---- gather quad keys in bins >= binSel ----
#pragma unroll
    for (int q = 0; q < 6; q++) {
        u32 key = tv[q];
        if ((int)(key >> 21) >= binSel) {
            int pos = atomicAdd(&s_gcnt, 1);
            if (pos < QCAP) s_g32[pos] = key;
        }
    }
    __syncthreads();
    const int qcnt = min(s_gcnt, QCAP);
    const int gex  = qcnt * 4;           // expanded candidate count
    if (tid == 0) {
        int sn = 64;
        while (sn < gex) sn <<= 1;
        s_snum = sn;
    }
    __syncthreads();
    const int snum = s_snum;

    // ---- expand quads -> exact element keys (alias stage smem as sort buf) ----
    u64* s_sort = (u64*)s_stage;
    u64 my = 0ull;
    if (tid < gex) {
        u32 qk = s_g32[tid >> 2];
        int idx = ((int)(qk & 0x1FFFu)) * 4 + (tid & 3);
        float x = __ldg(rowp + idx) * invT;
        my = (((u64)f2s(x)) << 32) | (u32)idx;
    }
    if (tid < snum) s_sort[tid] = my;    // pads = 0, sort last

    // ---- bitonic sort (descending) over snum entries ----
    for (int k = 2; k <= snum; k <<= 1) {
        for (int j2 = k >> 1; j2 > 0; j2 >>= 1) {
            __syncthreads();
            if (tid < snum) {
                int ixj = tid ^ j2;
                if (ixj > tid) {
                    u64 a = s_sort[tid], b = s_sort[ixj];
                    bool desc = ((tid & k) == 0);
                    if (desc ? (a < b) : (a > b)) { s_sort[tid] = b; s_sort[ixj] = a; }
                }
            }
        }
    }
    __syncthreads();

    // ---- top-p prefix rule over sorted ranks, capped at Kw ----
    const int lim = min(Kw, gex);
    float e = 0.0f;
    if (tid < lim) e = __expf(s2f((u32)(s_sort[tid] >> 32)));
    float einc = block_scan_f32(e, s_f16, tid);
    s_pref[tid] = einc;
    {
        float cumex = einc - e;
        float thresh = topP * s_Z;
        if (tid >= 1 && tid < lim && cumex > thresh)
            atomicMin(&s_vmin, tid);
    }
    __syncthreads();
    const int kcnt = min(s_vmin, lim);
    const float Zp = s_pref[kcnt - 1];

    // ---- Gumbel-argmax over kept set ----
    u64 best = 0ull;
    if (tid < kcnt) {
        u64 cnd = s_sort[tid];
        u32 idx = (u32)cnd;
        float v = s2f((u32)(cnd >> 32));
        float g = __ldg(&gumbel[(size_t)row * VOCAB + idx]);
        best = (((u64)f2s(v + g)) << 32) | (u32)tid;
    }
#pragma unroll
    for (int off = 16; off; off >>= 1) {
        u64 o = __shfl_down_sync(0xffffffffu, best, off);
        if (o > best) best = o;
    }
    if (lane == 0) s_red64[wid] = best;
    __syncthreads();
    if (tid == 0) {
        u64 b = 0ull;
        for (int w = 0; w < 16; w++) if (s_red64[w] > b) b = s_red64[w];
        int sel = (int)(u32)b;
        u64 cnd = s_sort[sel];
        float conf = __expf(s2f((u32)(cnd >> 32))) / Zp;
        out[row]         = conf;
        out[N + row]     = (float)(u32)cnd;
        out[2 * N + row] = conf;

        __threadfence();
        int prev = atomicAdd(&g_done_ctr, 1);
        s_last = (prev == N - 1) ? 1 : 0;
    }
    __syncthreads();

    // ---- last block: cross-row finalize (accepted flags) ----
    if (s_last) {
        __threadfence();
        const float thr = *thr_p;
        u64 fb = 0ull; int anyl = 0;
        float cv[4];
#pragma unroll
        for (int q = 0; q < 4; q++) {
            int r = tid + q * TPB;
            float c = (r < N) ? out[r] : -1.0f;
            cv[q] = c;
            if (r < N) {
                if (c > thr) anyl = 1;
                u64 k = (((u64)f2s(c)) << 32) | (u32)(N - 1 - r);
                if (k > fb) fb = k;
            }
        }
#pragma unroll
        for (int off = 16; off; off >>= 1) {
            u64 o = __shfl_down_sync(0xffffffffu, fb, off);
            if (o > fb) fb = o;
        }
        int anyw = __any_sync(0xffffffffu, anyl);
        if (lane == 0) { s_red64[wid] = fb; s_t16[wid] = (u32)anyw; }
        __syncthreads();
        if (tid == 0) {
            u64 b = 0ull; u32 a = 0;
            for (int w = 0; w < 16; w++) {
                if (s_red64[w] > b) b = s_red64[w];
                a |= s_t16[w];
            }
            s_red64[0] = b;
            s_t16[0] = a;
            g_done_ctr = 0;
        }
        __syncthreads();
        const int argrow = N - 1 - (int)(u32)s_red64[0];
        const int anyh = (int)s_t16[0];
#pragma unroll
        for (int q = 0; q < 4; q++) {
            int r = tid + q * TPB;
            if (r < N)
                out[3 * N + r] = anyh ? ((cv[q] > thr) ? 1.0f : 0.0f)
                                      : ((r == argrow) ? 1.0f : 0.0f);
        }
    }
}

extern "C" void kernel_launch(void* const* d_in, const int* in_sizes, int n_in,
                              void* d_out, int out_size)
{
    const float* logits = (const float*)d_in[0];
    const float* gumbel = (const float*)d_in[1];
    const float* temp   = (const float*)d_in[2];
    const float* topp   = (const float*)d_in[3];
    const int*   topk   = (const int*)  d_in[4];
    const float* thr    = (const float*)d_in[5];

    int N = in_sizes[0] / VOCAB;
    float* out = (float*)d_out;

    sampler_row_kernel<<<N, TPB>>>(logits, gumbel, temp, topp, topk, thr, out, N);
}

// round 8
// speedup vs baseline: 1.1471x; 1.1471x over previous
#include <cuda_runtime.h>
#include <cstdint>

#define VOCAB   32000
#define VWORDS  8000          // VOCAB / 4 (float4 words), < 2^13
#define TPB     512
#define SWORDS  512           // float4 words per stage (8 KB)
#define NSTAGES 16
#define DEPTH   4
#define NBINS   2048
#define QCAP    128           // max gathered quads (-> 512 candidates)

typedef unsigned long long u64;
typedef unsigned int       u32;

__device__ int g_done_ctr = 0;

__device__ __forceinline__ u32 f2s(float f) {
    u32 b = __float_as_uint(f);
    return (b & 0x80000000u) ? ~b : (b | 0x80000000u);
}
__device__ __forceinline__ float s2f(u32 u) {
    u32 b = (u & 0x80000000u) ? (u & 0x7fffffffu) : ~u;
    return __uint_as_float(b);
}

__device__ __forceinline__ u32 block_scan_u32(u32 v, u32* smem16, int tid) {
    int lane = tid & 31, wid = tid >> 5;
    u32 x = v;
#pragma unroll
    for (int o = 1; o < 32; o <<= 1) {
        u32 t = __shfl_up_sync(0xffffffffu, x, o);
        if (lane >= o) x += t;
    }
    if (lane == 31) smem16[wid] = x;
    __syncthreads();
    if (wid == 0) {
        u32 w = (lane < 16) ? smem16[lane] : 0u;
#pragma unroll
        for (int o = 1; o < 16; o <<= 1) {
            u32 t = __shfl_up_sync(0xffffffffu, w, o);
            if (lane >= o) w += t;
        }
        if (lane < 16) smem16[lane] = w;
    }
    __syncthreads();
    return x + (wid ? smem16[wid - 1] : 0u);
}

// branchless descending top-6 insert; alternate int/float minmax pipes.
__device__ __forceinline__ void ins6(u32 k, u32 (&tv)[6]) {
#pragma unroll
    for (int q = 0; q < 6; q++) {
        if (q & 1) {
            float a = __uint_as_float(tv[q]), b = __uint_as_float(k);
            float hi = fmaxf(a, b), lo = fminf(a, b);
            tv[q] = __float_as_uint(hi); k = __float_as_uint(lo);
        } else {
            u32 hi = max(tv[q], k), lo = min(tv[q], k);
            tv[q] = hi; k = lo;
        }
    }
}

__device__ __forceinline__ float ex2f(float y) {
    float r;
    asm("ex2.approx.f32 %0, %1;" : "=f"(r) : "f"(y));
    return r;
}

// 4 elements: Z accumulate + single quad-max key insert
__device__ __forceinline__ void proc4(float4 v, int j, float c1,
                                      float& z0, float& z1, float& z2, float& z3,
                                      u32 (&tv)[6]) {
    float e0 = ex2f(v.x * c1), e1 = ex2f(v.y * c1);
    float e2 = ex2f(v.z * c1), e3 = ex2f(v.w * c1);
    z0 += e0; z1 += e1; z2 += e2; z3 += e3;
    float m = fmaxf(fmaxf(e0, e1), fmaxf(e2, e3));
    u32 k = (__float_as_uint(m) & 0xFFFFE000u) | (u32)j;
    ins6(k, tv);
}

__global__ __launch_bounds__(TPB, 3)
void sampler_row_kernel(const float* __restrict__ logits,
                        const float* __restrict__ gumbel,
                        const float* __restrict__ temp_p,
                        const float* __restrict__ topp_p,
                        const int*   __restrict__ topk_p,
                        const float* __restrict__ thr_p,
                        float* __restrict__ out, int N)
{
    __shared__ float4 s_stage[DEPTH][SWORDS];   // 32 KB; reused as key buffer
    __shared__ u32    s_hist[NBINS];            // 8 KB
    __shared__ u32    s_g32[QCAP];              // 512 B (gathered quad keys)
    __shared__ float  s_e[512];                 // 2 KB (candidate exps)
    __shared__ u32    s_t16[16];
    __shared__ u64    s_red64[16];
    __shared__ float  s_redf[16];
    __shared__ float  s_Z;
    __shared__ int    s_bin, s_gcnt, s_last;

    const int tid  = threadIdx.x;
    const int row  = blockIdx.x;
    const int wid  = tid >> 5;
    const int lane = tid & 31;

    const float invT = 1.0f / (*temp_p);
    const float c1   = 1.44269504088896341f * invT;   // log2(e)/T
    const float topP = *topp_p;
    int Kw = *topk_p;
    Kw = max(1, min(Kw, 512));
    const int KQ = min(Kw, QCAP);    // quad-rank target

    const float* rowp = logits + (size_t)row * VOCAB;
    const float4* rp  = (const float4*)rowp;

    if (tid == 0) s_gcnt = 0;
#pragma unroll
    for (int q = 0; q < NBINS / TPB; q++) s_hist[tid + q * TPB] = 0u;

    u32 tv[6];
#pragma unroll
    for (int q = 0; q < 6; q++) tv[q] = 0u;
    float z0 = 0.f, z1 = 0.f, z2 = 0.f, z3 = 0.f;

#define ISSUE(s)                                                              \
    do {                                                                      \
        int _j = (s) * SWORDS + tid;                                          \
        if ((s) < NSTAGES && _j < VWORDS) {                                   \
            u32 _dst = (u32)__cvta_generic_to_shared(                         \
                &s_stage[(s) & (DEPTH - 1)][tid]);                            \
            asm volatile("cp.async.cg.shared.global [%0], [%1], 16;"          \
                         :: "r"(_dst), "l"(rp + _j));                         \
        }                                                                     \
        asm volatile("cp.async.commit_group;");                               \
    } while (0)

    ISSUE(0); ISSUE(1); ISSUE(2); ISSUE(3);

#pragma unroll 1
    for (int s = 0; s < NSTAGES; s++) {
        asm volatile("cp.async.wait_group %0;" :: "n"(DEPTH - 1));
        int j = s * SWORDS + tid;
        if (j < VWORDS) {
            float4 v = s_stage[s & (DEPTH - 1)][tid];
            proc4(v, j, c1, z0, z1, z2, z3, tv);
        }
        ISSUE(s + DEPTH);
    }
    asm volatile("cp.async.wait_group 0;");

    float zsum = (z0 + z1) + (z2 + z3);

    // ---- block-reduce Z ----
#pragma unroll
    for (int off = 16; off; off >>= 1)
        zsum += __shfl_down_sync(0xffffffffu, zsum, off);
    if (lane == 0) s_redf[wid] = zsum;
    __syncthreads();
    if (tid == 0) {
        float z = 0.0f;
        for (int w = 0; w < 16; w++) z += s_redf[w];
        s_Z = z;
    }

    // ---- histogram of quad keys (top 11 bits) ----
#pragma unroll
    for (int q = 0; q < 6; q++)
        atomicAdd(&s_hist[tv[q] >> 21], 1u);
    __syncthreads();

    // ---- suffix scan from highest bin; locate rank-KQ bin ----
    u32 c4[4]; u32 tsum = 0;
#pragma unroll
    for (int q = 0; q < 4; q++) {
        int bin = (NBINS - 1) - (tid * 4 + q);
        c4[q] = s_hist[bin];
        tsum += c4[q];
    }
    u32 incl = block_scan_u32(tsum, s_t16, tid);
    {
        u32 cum = incl - tsum;
#pragma unroll
        for (int q = 0; q < 4; q++) {
            if (cum < (u32)KQ && cum + c4[q] >= (u32)KQ)
                s_bin = (NBINS - 1) - (tid * 4 + q);
            cum += c4[q];
        }
    }
    __syncthreads();
    const int binSel = s_bin;

    // ---- gather quad keys in bins >= binSel ----
#pragma unroll
    for (int q = 0; q < 6; q++) {
        u32 key = tv[q];
        if ((int)(key >> 21) >= binSel) {
            int pos = atomicAdd(&s_gcnt, 1);
            if (pos < QCAP) s_g32[pos] = key;
        }
    }
    __syncthreads();
    const int qcnt = min(s_gcnt, QCAP);
    const int gex  = qcnt * 4;           // expanded candidate count (mult of 4)

    // ---- expand quads -> exact keys + exps (keys alias stage smem) ----
    u64* s_key = (u64*)s_stage;
    u64 myk = 0ull; float mye = 0.0f, myx = 0.0f; int myidx = 0;
    if (tid < gex) {
        u32 qk = s_g32[tid >> 2];
        myidx = ((int)(qk & 0x1FFFu)) * 4 + (tid & 3);
        myx = __ldg(rowp + myidx) * invT;
        mye = __expf(myx);
        // tie-break: smaller idx -> larger low word -> higher rank (stable argsort)
        myk = (((u64)f2s(myx)) << 32) | (u32)(VOCAB - myidx);
        s_key[tid] = myk;
        s_e[tid] = mye;
    }
    __syncthreads();

    // ---- all-pairs rank + prefix-sum: R = #{key > mine}, S = sum of their exps
    int R = 0; float S = 0.0f;
    if (tid < gex) {
#pragma unroll 4
        for (int j = 0; j < gex; j++) {
            u64 kj = s_key[j];
            bool gt = kj > myk;
            R += gt ? 1 : 0;
            S += gt ? s_e[j] : 0.0f;
        }
    }
    const bool kept = (tid < gex) && (R < Kw) && (S <= topP * s_Z);

    // ---- Zp reduction + Gumbel-argmax over kept set (fused) ----
    float zc = kept ? mye : 0.0f;
    u64 best = 0ull;
    if (kept) {
        float g = __ldg(&gumbel[(size_t)row * VOCAB + myidx]);
        best = (((u64)f2s(myx + g)) << 32) | (u32)tid;
    }
#pragma unroll
    for (int off = 16; off; off >>= 1) {
        zc += __shfl_down_sync(0xffffffffu, zc, off);
        u64 o = __shfl_down_sync(0xffffffffu, best, off);
        if (o > best) best = o;
    }
    if (lane == 0) { s_redf[wid] = zc; s_red64[wid] = best; }
    __syncthreads();
    if (tid == 0) {
        float Zp = 0.0f; u64 b = 0ull;
        for (int w = 0; w < 16; w++) {
            Zp += s_redf[w];
            if (s_red64[w] > b) b = s_red64[w];
        }
        int sel = (int)(u32)b;
        int selidx = VOCAB - (int)(u32)(s_key[sel] & 0xFFFFFFFFu);
        float conf = s_e[sel] / Zp;
        out[row]         = conf;
        out[N + row]     = (float)selidx;
        out[2 * N + row] = conf;

        __threadfence();
        int prev = atomicAdd(&g_done_ctr, 1);
        s_last = (prev == N - 1) ? 1 : 0;
    }
    __syncthreads();

    // ---- last block: cross-row finalize (accepted flags) ----
    if (s_last) {
        __threadfence();
        const float thr = *thr_p;
        u64 fb = 0ull; int anyl = 0;
        float cv[4];
#pragma unroll
        for (int q = 0; q < 4; q++) {
            int r = tid + q * TPB;
            float c = (r < N) ? out[r] : -1.0f;
            cv[q] = c;
            if (r < N) {
                if (c > thr) anyl = 1;
                u64 k = (((u64)f2s(c)) << 32) | (u32)(N - 1 - r);
                if (k > fb) fb = k;
            }
        }
#pragma unroll
        for (int off = 16; off; off >>= 1) {
            u64 o = __shfl_down_sync(0xffffffffu, fb, off);
            if (o > fb) fb = o;
        }
        int anyw = __any_sync(0xffffffffu, anyl);
        if (lane == 0) { s_red64[wid] = fb; s_t16[wid] = (u32)anyw; }
        __syncthreads();
        if (tid == 0) {
            u64 b = 0ull; u32 a = 0;
            for (int w = 0; w < 16; w++) {
                if (s_red64[w] > b) b = s_red64[w];
                a |= s_t16[w];
            }
            s_red64[0] = b;
            s_t16[0] = a;
            g_done_ctr = 0;
        }
        __syncthreads();
        const int argrow = N - 1 - (int)(u32)s_red64[0];
        const int anyh = (int)s_t16[0];
#pragma unroll
        for (int q = 0; q < 4; q++) {
            int r = tid + q * TPB;
            if (r < N)
                out[3 * N + r] = anyh ? ((cv[q] > thr) ? 1.0f : 0.0f)
                                      : ((r == argrow) ? 1.0f : 0.0f);
        }
    }
}

extern "C" void kernel_launch(void* const* d_in, const int* in_sizes, int n_in,
                              void* d_out, int out_size)
{
    const float* logits = (const float*)d_in[0];
    const float* gumbel = (const float*)d_in[1];
    const float* temp   = (const float*)d_in[2];
    const float* topp   = (const float*)d_in[3];
    const int*   topk   = (const int*)  d_in[4];
    const float* thr    = (const float*)d_in[5];

    int N = in_sizes[0] / VOCAB;
    float* out = (float*)d_out;

    sampler_row_kernel<<<N, TPB>>>(logits, gumbel, temp, topp, topk, thr, out, N);
}

// round 10
// speedup vs baseline: 1.4845x; 1.2942x over previous
#include <cuda_runtime.h>
#include <cstdint>

#define VOCAB   32000
#define VWORDS  8000          // VOCAB / 4 (float4 words), < 2^13
#define TPB     512
#define SWORDS  512           // float4 words per stage (8 KB)
#define NSTAGES 16
#define DEPTH   4
#define NBINS   2048
#define QCAP    128           // max gathered quads (-> 512 candidates)
#define MCAP    192           // max compact (element-level) candidates

typedef unsigned long long u64;
typedef unsigned int       u32;

__device__ int g_done_ctr = 0;

__device__ __forceinline__ u32 f2s(float f) {
    u32 b = __float_as_uint(f);
    return (b & 0x80000000u) ? ~b : (b | 0x80000000u);
}

__device__ __forceinline__ u32 block_scan_u32(u32 v, u32* smem16, int tid) {
    int lane = tid & 31, wid = tid >> 5;
    u32 x = v;
#pragma unroll
    for (int o = 1; o < 32; o <<= 1) {
        u32 t = __shfl_up_sync(0xffffffffu, x, o);
        if (lane >= o) x += t;
    }
    if (lane == 31) smem16[wid] = x;
    __syncthreads();
    if (wid == 0) {
        u32 w = (lane < 16) ? smem16[lane] : 0u;
#pragma unroll
        for (int o = 1; o < 16; o <<= 1) {
            u32 t = __shfl_up_sync(0xffffffffu, w, o);
            if (lane >= o) w += t;
        }
        if (lane < 16) smem16[lane] = w;
    }
    __syncthreads();
    return x + (wid ? smem16[wid - 1] : 0u);
}

// branchless descending top-6 insert; alternate int/float minmax pipes.
__device__ __forceinline__ void ins6(u32 k, u32 (&tv)[6]) {
#pragma unroll
    for (int q = 0; q < 6; q++) {
        if (q & 1) {
            float a = __uint_as_float(tv[q]), b = __uint_as_float(k);
            float hi = fmaxf(a, b), lo = fminf(a, b);
            tv[q] = __float_as_uint(hi); k = __float_as_uint(lo);
        } else {
            u32 hi = max(tv[q], k), lo = min(tv[q], k);
            tv[q] = hi; k = lo;
        }
    }
}

__device__ __forceinline__ float ex2f(float y) {
    float r;
    asm("ex2.approx.f32 %0, %1;" : "=f"(r) : "f"(y));
    return r;
}

// 4 elements: Z accumulate + single quad-max key insert
__device__ __forceinline__ void proc4(float4 v, int j, float c1,
                                      float& z0, float& z1, float& z2, float& z3,
                                      u32 (&tv)[6]) {
    float e0 = ex2f(v.x * c1), e1 = ex2f(v.y * c1);
    float e2 = ex2f(v.z * c1), e3 = ex2f(v.w * c1);
    z0 += e0; z1 += e1; z2 += e2; z3 += e3;
    float m = fmaxf(fmaxf(e0, e1), fmaxf(e2, e3));
    u32 k = (__float_as_uint(m) & 0xFFFFE000u) | (u32)j;
    ins6(k, tv);
}

__global__ __launch_bounds__(TPB, 3)
void sampler_row_kernel(const float* __restrict__ logits,
                        const float* __restrict__ gumbel,
                        const float* __restrict__ temp_p,
                        const float* __restrict__ topp_p,
                        const int*   __restrict__ topk_p,
                        const float* __restrict__ thr_p,
                        float* __restrict__ out, int N)
{
    __shared__ float4 s_stage[DEPTH][SWORDS];   // 32 KB (mainloop only)
    __shared__ u32    s_hist[NBINS];            // 8 KB (reused for both tiers)
    __shared__ u32    s_g32[QCAP];              // gathered quad keys
    __shared__ u64    s_ckey[MCAP];             // compact candidate keys
    __shared__ float  s_cexp[MCAP];
    __shared__ float  s_cx[MCAP];
    __shared__ int    s_cidx[MCAP];
    __shared__ u32    s_t16[16];
    __shared__ u64    s_red64[16];
    __shared__ float  s_redf[16];
    __shared__ float  s_Z;
    __shared__ int    s_bin, s_gcnt, s_cnt2, s_last;

    const int tid  = threadIdx.x;
    const int row  = blockIdx.x;
    const int wid  = tid >> 5;
    const int lane = tid & 31;

    const float invT = 1.0f / (*temp_p);
    const float c1   = 1.44269504088896341f * invT;   // log2(e)/T
    const float topP = *topp_p;
    int Kw = *topk_p;
    Kw = max(1, min(Kw, 512));
    const int KQ = min(Kw, QCAP);          // quad-rank target
    const int Ke = min(Kw, 128);           // element-rank target (compact tier)

    const float* rowp = logits + (size_t)row * VOCAB;
    const float4* rp  = (const float4*)rowp;

    if (tid == 0) { s_gcnt = 0; s_cnt2 = 0; }
#pragma unroll
    for (int q = 0; q < NBINS / TPB; q++) s_hist[tid + q * TPB] = 0u;

    u32 tv[6];
#pragma unroll
    for (int q = 0; q < 6; q++) tv[q] = 0u;
    float z0 = 0.f, z1 = 0.f, z2 = 0.f, z3 = 0.f;

#define ISSUE(s)                                                              \
    do {                                                                      \
        int _j = (s) * SWORDS + tid;                                          \
        if ((s) < NSTAGES && _j < VWORDS) {                                   \
            u32 _dst = (u32)__cvta_generic_to_shared(                         \
                &s_stage[(s) & (DEPTH - 1)][tid]);                            \
            asm volatile("cp.async.cg.shared.global [%0], [%1], 16;"          \
                         :: "r"(_dst), "l"(rp + _j));                         \
        }                                                                     \
        asm volatile("cp.async.commit_group;");                               \
    } while (0)

    ISSUE(0); ISSUE(1); ISSUE(2); ISSUE(3);

#pragma unroll 1
    for (int s = 0; s < NSTAGES; s++) {
        asm volatile("cp.async.wait_group %0;" :: "n"(DEPTH - 1));
        int j = s * SWORDS + tid;
        if (j < VWORDS) {
            float4 v = s_stage[s & (DEPTH - 1)][tid];
            proc4(v, j, c1, z0, z1, z2, z3, tv);
        }
        ISSUE(s + DEPTH);
    }
    asm volatile("cp.async.wait_group 0;");

    float zsum = (z0 + z1) + (z2 + z3);

    // ---- block-reduce Z ----
#pragma unroll
    for (int off = 16; off; off >>= 1)
        zsum += __shfl_down_sync(0xffffffffu, zsum, off);
    if (lane == 0) s_redf[wid] = zsum;
    __syncthreads();
    if (tid == 0) {
        float z = 0.0f;
        for (int w = 0; w < 16; w++) z += s_redf[w];
        s_Z = z;
    }

    // ---- tier 1: histogram of quad keys (top 11 bits) ----
#pragma unroll
    for (int q = 0; q < 6; q++)
        atomicAdd(&s_hist[tv[q] >> 21], 1u);
    __syncthreads();

    // suffix scan from highest bin; locate rank-KQ bin
    u32 c4[4]; u32 tsum = 0;
#pragma unroll
    for (int q = 0; q < 4; q++) {
        int bin = (NBINS - 1) - (tid * 4 + q);
        c4[q] = s_hist[bin];
        tsum += c4[q];
    }
    u32 incl = block_scan_u32(tsum, s_t16, tid);
    {
        u32 cum = incl - tsum;
#pragma unroll
        for (int q = 0; q < 4; q++) {
            if (cum < (u32)KQ && cum + c4[q] >= (u32)KQ)
                s_bin = (NBINS - 1) - (tid * 4 + q);
            cum += c4[q];
        }
    }
    __syncthreads();
    const int binSel = s_bin;

    // gather quad keys in bins >= binSel
#pragma unroll
    for (int q = 0; q < 6; q++) {
        u32 key = tv[q];
        if ((int)(key >> 21) >= binSel) {
            int pos = atomicAdd(&s_gcnt, 1);
            if (pos < QCAP) s_g32[pos] = key;
        }
    }
    __syncthreads();
    const int qcnt = min(s_gcnt, QCAP);
    const int gex  = qcnt * 4;           // expanded candidate count

    // ---- tier 2: expand quads in registers; element-level cutoff ----
    u64 myk = 0ull; float mye = 0.0f, myx = 0.0f; int myidx = 0; u32 mybits = 0;
    if (tid < gex) {
        u32 qk = s_g32[tid >> 2];
        myidx = ((int)(qk & 0x1FFFu)) * 4 + (tid & 3);
        myx = __ldg(rowp + myidx) * invT;
        mye = __expf(myx);
        mybits = f2s(myx);
        // tie-break: smaller idx -> larger low word -> higher rank
        myk = (((u64)mybits) << 32) | (u32)(VOCAB - myidx);
    }
    // clear histogram for reuse (tier-1 reads are complete)
#pragma unroll
    for (int q = 0; q < NBINS / TPB; q++) s_hist[tid + q * TPB] = 0u;
    __syncthreads();

    if (tid < gex) atomicAdd(&s_hist[mybits >> 21], 1u);
    __syncthreads();

    // suffix scan; locate element rank-Ke bin
    tsum = 0;
#pragma unroll
    for (int q = 0; q < 4; q++) {
        int bin = (NBINS - 1) - (tid * 4 + q);
        c4[q] = s_hist[bin];
        tsum += c4[q];
    }
    incl = block_scan_u32(tsum, s_t16, tid);
    {
        u32 cum = incl - tsum;
#pragma unroll
        for (int q = 0; q < 4; q++) {
            if (cum < (u32)Ke && cum + c4[q] >= (u32)Ke)
                s_bin = (NBINS - 1) - (tid * 4 + q);
            cum += c4[q];
        }
    }
    __syncthreads();
    const int binSel2 = s_bin;

    // gather compact candidates (rank provably < Ke + bin overshoot)
    if (tid < gex && (int)(mybits >> 21) >= binSel2) {
        int pos = atomicAdd(&s_cnt2, 1);
        if (pos < MCAP) {
            s_ckey[pos] = myk;
            s_cexp[pos] = mye;
            s_cx[pos]   = myx;
            s_cidx[pos] = myidx;
        }
    }
    __syncthreads();
    const int mcnt = min(s_cnt2, MCAP);

    // ---- all-pairs rank + prefix over compact set (~64 entries, 2 warps) ----
    float zc = 0.0f; u64 best = 0ull;
    if (tid < mcnt) {
        u64 mk = s_ckey[tid];
        int R = 0; float S = 0.0f;
        for (int j = 0; j < mcnt; j++) {
            u64 kj = s_ckey[j];
            bool gt = kj > mk;
            R += gt ? 1 : 0;
            S += gt ? s_cexp[j] : 0.0f;
        }
        if (R < Kw && S <= topP * s_Z) {
            zc = s_cexp[tid];
            float g = __ldg(&gumbel[(size_t)row * VOCAB + s_cidx[tid]]);
            best = (((u64)f2s(s_cx[tid] + g)) << 32) | (u32)tid;
        }
    }
#pragma unroll
    for (int off = 16; off; off >>= 1) {
        zc += __shfl_down_sync(0xffffffffu, zc, off);
        u64 o = __shfl_down_sync(0xffffffffu, best, off);
        if (o > best) best = o;
    }
    if (lane == 0) { s_redf[wid] = zc; s_red64[wid] = best; }
    __syncthreads();
    if (tid == 0) {
        float Zp = 0.0f; u64 b = 0ull;
        for (int w = 0; w < 16; w++) {
            Zp += s_redf[w];
            if (s_red64[w] > b) b = s_red64[w];
        }
        int sel = (int)(u32)b;
        float conf = s_cexp[sel] / Zp;
        out[row]         = conf;
        out[N + row]     = (float)s_cidx[sel];
        out[2 * N + row] = conf;

        __threadfence();
        int prev = atomicAdd(&g_done_ctr, 1);
        s_last = (prev == N - 1) ? 1 : 0;
    }
    __syncthreads();

    // ---- last block: cross-row finalize (accepted flags) ----
    if (s_last) {
        __threadfence();
        const float thr = *thr_p;
        u64 fb = 0ull; int anyl = 0;
        float cv[4];
#pragma unroll
        for (int q = 0; q < 4; q++) {
            int r = tid + q * TPB;
            float c = (r < N) ? out[r] : -1.0f;
            cv[q] = c;
            if (r < N) {
                if (c > thr) anyl = 1;
                u64 k = (((u64)f2s(c)) << 32) | (u32)(N - 1 - r);
                if (k > fb) fb = k;
            }
        }
#pragma unroll
        for (int off = 16; off; off >>= 1) {
            u64 o = __shfl_down_sync(0xffffffffu, fb, off);
            if (o > fb) fb = o;
        }
        int anyw = __any_sync(0xffffffffu, anyl);
        if (lane == 0) { s_red64[wid] = fb; s_t16[wid] = (u32)anyw; }
        __syncthreads();
        if (tid == 0) {
            u64 b = 0ull; u32 a = 0;
            for (int w = 0; w < 16; w++) {
                if (s_red64[w] > b) b = s_red64[w];
                a |= s_t16[w];
            }
            s_red64[0] = b;
            s_t16[0] = a;
            g_done_ctr = 0;
        }
        __syncthreads();
        const int argrow = N - 1 - (int)(u32)s_red64[0];
        const int anyh = (int)s_t16[0];
#pragma unroll
        for (int q = 0; q < 4; q++) {
            int r = tid + q * TPB;
            if (r < N)
                out[3 * N + r] = anyh ? ((cv[q] > thr) ? 1.0f : 0.0f)
                                      : ((r == argrow) ? 1.0f : 0.0f);
        }
    }
}

extern "C" void kernel_launch(void* const* d_in, const int* in_sizes, int n_in,
                              void* d_out, int out_size)
{
    const float* logits = (const float*)d_in[0];
    const float* gumbel = (const float*)d_in[1];
    const float* temp   = (const float*)d_in[2];
    const float* topp   = (const float*)d_in[3];
    const int*   topk   = (const int*)  d_in[4];
    const float* thr    = (const float*)d_in[5];

    int N = in_sizes[0] / VOCAB;
    float* out = (float*)d_out;

    sampler_row_kernel<<<N, TPB>>>(logits, gumbel, temp, topp, topk, thr, out, N);
}